// round 7
// baseline (speedup 1.0000x reference)
#include <cuda_runtime.h>
#include <math.h>

// Problem constants
#define FS_F      100.0f
#define N_FILT    12
#define N_CH      27
#define KDIM      5
#define T_IN      65536
#define T_OUT     65532          // T_IN - KDIM + 1
#define THREADS   256
#define UNIT      1024           // outputs per unit = THREADS * 4
#define UNITS_PER_ROW 64         // 65536 / 1024
#define N_ROWS    (8 * N_CH)     // 216 (b,c) rows
#define N_UNITS   (N_ROWS * UNITS_PER_ROW)   // 13824
#define GRID      592            // ~2 persistent blocks per SM (148 SMs)
#define N_FILT_TOT (N_CH * N_FILT)           // 324

__global__ __launch_bounds__(THREADS)
void sinc_conv_kernel(const float* __restrict__ x,
                      const float* __restrict__ filt_low,
                      const float* __restrict__ filt_band,
                      float* __restrict__ out)
{
    // all 324 filters, 5 taps each (padded to 6 for write-bank spread)
    __shared__ float w[N_FILT_TOT][6];

    const int tid = threadIdx.x;

    // ---- build ALL filters once per block ----
    for (int ff = tid; ff < N_FILT_TOT; ff += THREADS) {
        const float PI2 = 6.28318530717958647692f;

        float beg = fabsf(filt_low [ff]) + 1.0f / FS_F;   // [C,F] row-major == ff
        float end = beg + fabsf(filt_band[ff]);

        // t_right = linspace(1,2,2)/FS = {0.01, 0.02}
        float aE1 = PI2 * FS_F * end * 0.01f;
        float aE2 = PI2 * FS_F * end * 0.02f;
        float aB1 = PI2 * FS_F * beg * 0.01f;
        float aB2 = PI2 * FS_F * beg * 0.02f;
        float yE1 = sinf(aE1) / aE1;
        float yE2 = sinf(aE2) / aE2;
        float yB1 = sinf(aB1) / aB1;
        float yB2 = sinf(aB2) / aB2;

        float e2 = 2.0f * end, b2 = 2.0f * beg;
        float bp0 = e2 * yE2 - b2 * yB2;   // outermost taps (symmetric)
        float bp1 = e2 * yE1 - b2 * yB1;
        float bp2 = e2        - b2;        // center (sinc(0)=1)

        float m = fmaxf(bp2, fmaxf(bp1, bp0));
        float inv_m = 1.0f / m;

        // Blackman-ish window, n = linspace(0, 5, 5) -> n_k = 1.25*k
        float win[KDIM];
        #pragma unroll
        for (int k = 0; k < KDIM; k++) {
            float n = 1.25f * (float)k;
            win[k] = 0.42f - 0.5f * cosf(PI2 * n / 5.0f)
                           + 0.08f * cosf(2.0f * PI2 * n / 5.0f);
        }

        w[ff][0] = bp0 * inv_m * win[0];
        w[ff][1] = bp1 * inv_m * win[1];
        w[ff][2] = bp2 * inv_m * win[2];
        w[ff][3] = bp1 * inv_m * win[3];
        w[ff][4] = bp0 * inv_m * win[4];
    }
    __syncthreads();

    // ---- persistent grid-stride loop over units, prefetch next unit's loads ----
    int u = blockIdx.x;

    // prologue: issue loads for first unit
    float4 a, d;
    bool p;
    int t0, bc;
    {
        bc = u >> 6;
        t0 = (u & 63) * UNIT + tid * 4;
        p  = (t0 <= T_OUT - 4);
        if (p) {
            const float* xr = x + (size_t)bc * T_IN + t0;
            a = __ldg((const float4*)xr);
            d = __ldg((const float4*)(xr + 4));
        }
    }

    #pragma unroll 1
    while (u < N_UNITS) {
        const int u_next = u + GRID;

        // prefetch next unit BEFORE draining this unit's stores
        float4 a2, d2;
        bool p2 = false;
        int t0n = 0, bcn = 0;
        if (u_next < N_UNITS) {
            bcn = u_next >> 6;
            t0n = (u_next & 63) * UNIT + tid * 4;
            p2  = (t0n <= T_OUT - 4);
            if (p2) {
                const float* xr = x + (size_t)bcn * T_IN + t0n;
                a2 = __ldg((const float4*)xr);
                d2 = __ldg((const float4*)(xr + 4));
            }
        }

        // process current unit: 12 filters x float4 stores
        if (p) {
            const float xv0 = a.x, xv1 = a.y, xv2 = a.z, xv3 = a.w;
            const float xv4 = d.x, xv5 = d.y, xv6 = d.z, xv7 = d.w;
            const int c = bc % N_CH;
            float* obase = out + ((size_t)bc * N_FILT) * T_OUT + t0;
            const float (*wc)[6] = &w[c * N_FILT];

            #pragma unroll
            for (int f = 0; f < N_FILT; f++) {
                const float c0 = wc[f][0], c1 = wc[f][1], c2 = wc[f][2],
                            c3 = wc[f][3], c4 = wc[f][4];
                float4 o;
                o.x = fmaf(xv0, c0, fmaf(xv1, c1, fmaf(xv2, c2, fmaf(xv3, c3, xv4 * c4))));
                o.y = fmaf(xv1, c0, fmaf(xv2, c1, fmaf(xv3, c2, fmaf(xv4, c3, xv5 * c4))));
                o.z = fmaf(xv2, c0, fmaf(xv3, c1, fmaf(xv4, c2, fmaf(xv5, c3, xv6 * c4))));
                o.w = fmaf(xv3, c0, fmaf(xv4, c1, fmaf(xv5, c2, fmaf(xv6, c3, xv7 * c4))));
                *((float4*)(obase + (size_t)f * T_OUT)) = o;
            }
        }

        // rotate pipeline
        a = a2; d = d2; p = p2; t0 = t0n; bc = bcn;
        u = u_next;
    }
}

extern "C" void kernel_launch(void* const* d_in, const int* in_sizes, int n_in,
                              void* d_out, int out_size)
{
    const float* x         = (const float*)d_in[0];
    const float* filt_low  = (const float*)d_in[1];
    const float* filt_band = (const float*)d_in[2];
    float* out             = (float*)d_out;

    sinc_conv_kernel<<<GRID, THREADS>>>(x, filt_low, filt_band, out);
}

// round 9
// speedup vs baseline: 1.2281x; 1.2281x over previous
#include <cuda_runtime.h>
#include <math.h>

// Problem constants
#define FS_F      100.0f
#define N_FILT    12
#define N_CH      27
#define KDIM      5
#define T_IN      65536
#define T_OUT     65532        // T_IN - KDIM + 1
#define TILE      1024
#define THREADS   128
#define N_TILES   64           // ceil(T_OUT / TILE)

__global__ __launch_bounds__(THREADS)
void sinc_conv_kernel(const float* __restrict__ x,
                      const float* __restrict__ filt_low,
                      const float* __restrict__ filt_band,
                      float* __restrict__ out)
{
    __shared__ float w[N_FILT][8];   // 5 taps per filter, padded

    const int blk  = blockIdx.x;
    const int tile = blk % N_TILES;
    const int bc   = blk / N_TILES;
    const int c    = bc % N_CH;
    const int b    = bc / N_CH;
    const int tid  = threadIdx.x;

    // ---- build the 12 filters for this channel (threads 0..11) ----
    if (tid < N_FILT) {
        const int f = tid;
        const float PI2 = 6.28318530717958647692f;

        float beg = fabsf(filt_low [c * N_FILT + f]) + 1.0f / FS_F;
        float end = beg + fabsf(filt_band[c * N_FILT + f]);

        // t_right = linspace(1,2,2)/FS = {0.01, 0.02}
        float aE1 = PI2 * FS_F * end * 0.01f;
        float aE2 = PI2 * FS_F * end * 0.02f;
        float aB1 = PI2 * FS_F * beg * 0.01f;
        float aB2 = PI2 * FS_F * beg * 0.02f;
        float yE1 = sinf(aE1) / aE1;
        float yE2 = sinf(aE2) / aE2;
        float yB1 = sinf(aB1) / aB1;
        float yB2 = sinf(aB2) / aB2;

        float e2 = 2.0f * end, b2 = 2.0f * beg;
        float bp0 = e2 * yE2 - b2 * yB2;   // outermost taps (symmetric)
        float bp1 = e2 * yE1 - b2 * yB1;
        float bp2 = e2        - b2;        // center (sinc(0)=1)

        float m = fmaxf(bp2, fmaxf(bp1, bp0));
        float inv_m = 1.0f / m;

        // Blackman-ish window, n = linspace(0, 5, 5) -> n_k = 1.25*k
        float win[KDIM];
        #pragma unroll
        for (int k = 0; k < KDIM; k++) {
            float n = 1.25f * (float)k;
            win[k] = 0.42f - 0.5f * cosf(PI2 * n / 5.0f)
                           + 0.08f * cosf(2.0f * PI2 * n / 5.0f);
        }

        w[f][0] = bp0 * inv_m * win[0];
        w[f][1] = bp1 * inv_m * win[1];
        w[f][2] = bp2 * inv_m * win[2];
        w[f][3] = bp1 * inv_m * win[3];
        w[f][4] = bp0 * inv_m * win[4];
    }
    __syncthreads();

    const float* xrow = x + ((size_t)b * N_CH + c) * T_IN;
    float* orow       = out + ((size_t)(b * N_CH + c) * N_FILT) * T_OUT;

    // two groups of 4 outputs per thread; prefetch ALL input loads first (MLP=4)
    const int t0 = tile * TILE + tid * 4;            // group 0
    const int t1 = t0 + THREADS * 4;                 // group 1

    const bool p0 = (t0 <= T_OUT - 4);
    const bool p1 = (t1 <= T_OUT - 4);

    float4 a0, d0, a1, d1;
    if (p0) { a0 = __ldg((const float4*)(xrow + t0));
              d0 = __ldg((const float4*)(xrow + t0 + 4)); }
    if (p1) { a1 = __ldg((const float4*)(xrow + t1));
              d1 = __ldg((const float4*)(xrow + t1 + 4)); }

    if (p0) {
        const float xv0 = a0.x, xv1 = a0.y, xv2 = a0.z, xv3 = a0.w;
        const float xv4 = d0.x, xv5 = d0.y, xv6 = d0.z, xv7 = d0.w;
        float* obase = orow + t0;
        #pragma unroll
        for (int f = 0; f < N_FILT; f++) {
            const float c0 = w[f][0], c1 = w[f][1], c2 = w[f][2],
                        c3 = w[f][3], c4 = w[f][4];
            float4 o;
            o.x = fmaf(xv0, c0, fmaf(xv1, c1, fmaf(xv2, c2, fmaf(xv3, c3, xv4 * c4))));
            o.y = fmaf(xv1, c0, fmaf(xv2, c1, fmaf(xv3, c2, fmaf(xv4, c3, xv5 * c4))));
            o.z = fmaf(xv2, c0, fmaf(xv3, c1, fmaf(xv4, c2, fmaf(xv5, c3, xv6 * c4))));
            o.w = fmaf(xv3, c0, fmaf(xv4, c1, fmaf(xv5, c2, fmaf(xv6, c3, xv7 * c4))));
            *((float4*)(obase + (size_t)f * T_OUT)) = o;
        }
    }

    if (p1) {
        const float xv0 = a1.x, xv1 = a1.y, xv2 = a1.z, xv3 = a1.w;
        const float xv4 = d1.x, xv5 = d1.y, xv6 = d1.z, xv7 = d1.w;
        float* obase = orow + t1;
        #pragma unroll
        for (int f = 0; f < N_FILT; f++) {
            const float c0 = w[f][0], c1 = w[f][1], c2 = w[f][2],
                        c3 = w[f][3], c4 = w[f][4];
            float4 o;
            o.x = fmaf(xv0, c0, fmaf(xv1, c1, fmaf(xv2, c2, fmaf(xv3, c3, xv4 * c4))));
            o.y = fmaf(xv1, c0, fmaf(xv2, c1, fmaf(xv3, c2, fmaf(xv4, c3, xv5 * c4))));
            o.z = fmaf(xv2, c0, fmaf(xv3, c1, fmaf(xv4, c2, fmaf(xv5, c3, xv6 * c4))));
            o.w = fmaf(xv3, c0, fmaf(xv4, c1, fmaf(xv5, c2, fmaf(xv6, c3, xv7 * c4))));
            *((float4*)(obase + (size_t)f * T_OUT)) = o;
        }
    }
}

extern "C" void kernel_launch(void* const* d_in, const int* in_sizes, int n_in,
                              void* d_out, int out_size)
{
    const float* x         = (const float*)d_in[0];
    const float* filt_low  = (const float*)d_in[1];
    const float* filt_band = (const float*)d_in[2];
    float* out             = (float*)d_out;

    const int grid = 8 * N_CH * N_TILES;  // 13824 blocks, 4 blocks/SM resident
    sinc_conv_kernel<<<grid, THREADS>>>(x, filt_low, filt_band, out);
}